// round 10
// baseline (speedup 1.0000x reference)
#include <cuda_runtime.h>
#include <math_constants.h>

#define NEMB  8192
#define NTOK  32768             // 8 * 4096
#define NBINS 256
#define BINW  (80.0f / 256.0f)  // n^2 bin width; chi^2_4 max over 8192 << 80
#define INVW  (256.0f / 80.0f)
#define SSTEP 32                // slots per quad per superstep (4 lanes x 8)
#define NBLK  148
#define NTHR  896               // 28 warps

// Dynamic smem layout (bytes)
#define OFF_SIDX 131072                   // after float4 tbl[8192]
#define OFF_UBS  147456                   // after u16 sidx[8192]
#define OFF_HIST 148512                   // float ubs[257] + pad
#define OFF_SOFF 149536
#define OFF_SCUR 150560
#define SMEM_TOTAL 151584

__device__ float d_part[NBLK];
__device__ int   d_done;                  // zero-init; self-resetting

__device__ __forceinline__ int bin_of(float n2) {
    int raw = (int)(n2 * INVW);
    raw = raw < 0 ? 0 : (raw > NBINS - 1 ? NBINS - 1 : raw);
    return NBINS - 1 - raw;               // bin 0 = highest norms
}

__global__ __launch_bounds__(NTHR, 1)
void vq_main_kernel(const float4* __restrict__ x4,
                    const float4* __restrict__ e4,
                    float* __restrict__ out) {
    extern __shared__ char smem[];
    float4*         s_tbl  = (float4*)smem;
    unsigned short* s_sidx = (unsigned short*)(smem + OFF_SIDX);
    float*          s_ubs  = (float*)(smem + OFF_UBS);
    int*            s_hist = (int*)(smem + OFF_HIST);
    int*            s_soff = (int*)(smem + OFF_SOFF);
    int*            s_scur = (int*)(smem + OFF_SCUR);
    __shared__ int   s_wsum[8];
    __shared__ float wred[NTHR / 32];
    __shared__ int   s_last;

    const int t    = threadIdx.x;
    const int lane = t & 31;
    const int wid  = t >> 5;
    const int sub  = lane & 3;
    const int tok  = ((int)blockIdx.x * 28 + wid) * 8 + (lane >> 2);
    const bool act = tok < NTOK;

    // Token load up-front: overlaps all of phase 1.
    float4 xv = act ? x4[tok] : make_float4(0.f, 0.f, 0.f, 0.f);
    const float nx = sqrtf(xv.x * xv.x + xv.y * xv.y + xv.z * xv.z + xv.w * xv.w)
                     * 1.000002f;                     // fp-guarded |x|

    // ---- Phase 1: per-block bin-sort of the table into smem ----
    for (int i = t; i < NBINS; i += NTHR) { s_hist[i] = 0; s_scur[i] = 0; }
    if (t == 0) { s_ubs[NEMB / 32] = 0.0f; s_last = 0; }
    __syncthreads();

    // histogram, 3 loads in flight
    for (int base = 0; base < NEMB; base += 3 * NTHR) {
        int i0 = base + t, i1 = i0 + NTHR, i2 = i1 + NTHR;
        float4 a, b, c;
        if (i0 < NEMB) a = e4[i0];
        if (i1 < NEMB) b = e4[i1];
        if (i2 < NEMB) c = e4[i2];
        if (i0 < NEMB) atomicAdd(&s_hist[bin_of(a.x*a.x + a.y*a.y + a.z*a.z + a.w*a.w)], 1);
        if (i1 < NEMB) atomicAdd(&s_hist[bin_of(b.x*b.x + b.y*b.y + b.z*b.z + b.w*b.w)], 1);
        if (i2 < NEMB) atomicAdd(&s_hist[bin_of(c.x*c.x + c.y*c.y + c.z*c.z + c.w*c.w)], 1);
    }
    __syncthreads();

    // exclusive prefix over 256 bins: 8 warp shfl-scans + tiny top scan
    if (wid < 8) {
        int cnt = s_hist[wid * 32 + lane];
        int v = cnt;
        #pragma unroll
        for (int o = 1; o < 32; o <<= 1) {
            int u = __shfl_up_sync(0xFFFFFFFFu, v, o);
            if (lane >= o) v += u;
        }
        if (lane == 31) s_wsum[wid] = v;
        s_soff[wid * 32 + lane] = v - cnt;
    }
    __syncthreads();
    if (wid == 0) {
        int c2 = (lane < 8) ? s_wsum[lane] : 0;
        int v2 = c2;
        #pragma unroll
        for (int o = 1; o < 8; o <<= 1) {
            int u = __shfl_up_sync(0xFFFFFFFFu, v2, o);
            if (lane >= o) v2 += u;
        }
        if (lane < 8) s_wsum[lane] = v2 - c2;
    }
    __syncthreads();
    for (int i = t; i < NBINS; i += NTHR) s_soff[i] += s_wsum[i >> 5];
    __syncthreads();

    // scatter, 3 loads in flight
    for (int base = 0; base < NEMB; base += 3 * NTHR) {
        int id[3]; float4 ev[3];
        #pragma unroll
        for (int j = 0; j < 3; j++) {
            id[j] = base + t + j * NTHR;
            if (id[j] < NEMB) ev[j] = e4[id[j]];
        }
        #pragma unroll
        for (int j = 0; j < 3; j++) {
            if (id[j] < NEMB) {
                float4 e = ev[j];
                int b = bin_of(e.x*e.x + e.y*e.y + e.z*e.z + e.w*e.w);
                int pos = s_soff[b] + atomicAdd(&s_scur[b], 1);
                s_tbl[pos]  = e;
                s_sidx[pos] = (unsigned short)id[j];
                if ((pos & 31) == 0)      // ub is non-increasing across slots
                    s_ubs[pos >> 5] = sqrtf((float)(NBINS - b) * BINW) * 1.000002f;
            }
        }
    }
    __syncthreads();

    // ---- Phase 2: pruned argmax scan, 4 lanes per token, lane-local stop ----
    float best = act ? -CUDART_INF_F : CUDART_INF_F; // inactive: stop at once
    int bidx = NEMB;

    int p = 0;                                        // warp-uniform base
    for (;;) {
        float ubn = s_ubs[(p >> 5) + 1];              // bound on slots >= p+32
        float d[8];
        #pragma unroll
        for (int i = 0; i < 8; i++) {
            float4 e = s_tbl[p + sub + 4 * i];        // 4 words/warp: broadcast
            // identical FMA chain as all validated rounds
            d[i] = fmaf(xv.x, e.x, fmaf(xv.y, e.y, fmaf(xv.z, e.z, xv.w * e.w)));
        }
        float om = fmaxf(fmaxf(fmaxf(d[0], d[1]), fmaxf(d[2], d[3])),
                         fmaxf(fmaxf(d[4], d[5]), fmaxf(d[6], d[7])));
        if (om >= best) {
            // rare slow path: exact first-max update, original-id tie-break
            #pragma unroll
            for (int i = 0; i < 8; i++) {
                int id = (int)s_sidx[p + sub + 4 * i];
                if (d[i] > best || (d[i] == best && id < bidx)) {
                    best = d[i]; bidx = id;
                }
            }
        }
        p += SSTEP;
        // lane-local certificate: lane's remaining slots all have
        // dot <= ubn*|x| < best <= merged best  => safe to skip
        bool stop = (p >= NEMB) || (ubn * nx < best);
        if (__all_sync(0xFFFFFFFFu, stop)) break;
    }

    // merge quad lanes: max value, ties -> lowest original index
    #pragma unroll
    for (int o = 1; o <= 2; o <<= 1) {
        float vo = __shfl_xor_sync(0xFFFFFFFFu, best, o);
        int   io = __shfl_xor_sync(0xFFFFFFFFu, bidx, o);
        if (vo > best || (vo == best && io < bidx)) { best = vo; bidx = io; }
    }

    float lsum = 0.0f;
    if (act && sub == 0) {
        float4 e = e4[bidx];
        lsum = fabsf(xv.x - e.x) + fabsf(xv.y - e.y)
             + fabsf(xv.z - e.z) + fabsf(xv.w - e.w);
    }

    // reduce: warp -> block
    #pragma unroll
    for (int o = 16; o; o >>= 1)
        lsum += __shfl_down_sync(0xFFFFFFFFu, lsum, o);
    if (lane == 0) wred[wid] = lsum;
    __syncthreads();

    // block partial -> d_part; last-arriving block finalizes (no init kernel)
    if (t == 0) {
        float s = 0.0f;
        #pragma unroll
        for (int i = 0; i < NTHR / 32; i++) s += wred[i];
        d_part[blockIdx.x] = s;
        __threadfence();
        if (atomicAdd(&d_done, 1) == NBLK - 1) s_last = 1;
    }
    __syncthreads();
    if (s_last && wid == 0) {
        float s = 0.0f;
        for (int i = lane; i < NBLK; i += 32) s += d_part[i];
        #pragma unroll
        for (int o = 16; o; o >>= 1)
            s += __shfl_down_sync(0xFFFFFFFFu, s, o);
        if (lane == 0) {
            out[0] = s * (2.0f / (float)(NTOK * 4));  // both L1 terms equal
            d_done = 0;                               // reset for graph replay
        }
    }
}

extern "C" void kernel_launch(void* const* d_in, const int* in_sizes, int n_in,
                              void* d_out, int out_size) {
    const float4* x   = (const float4*)d_in[0];   // [8,4096,4] f32
    const float4* emb = (const float4*)d_in[1];   // [8192,4] f32
    float* out = (float*)d_out;

    cudaFuncSetAttribute(vq_main_kernel,
                         cudaFuncAttributeMaxDynamicSharedMemorySize,
                         SMEM_TOTAL);

    vq_main_kernel<<<NBLK, NTHR, SMEM_TOTAL>>>(x, emb, out);
}

// round 11
// speedup vs baseline: 1.4100x; 1.4100x over previous
#include <cuda_runtime.h>
#include <math_constants.h>

#define NEMB  8192
#define NTOK  32768             // 8 * 4096
#define NBINS 512
#define BINW  (80.0f / 512.0f)  // n^2 bin width; chi^2_4 max over 8192 << 80
#define INVW  (512.0f / 80.0f)
#define SSTEP 32                // slots per quad per superstep (4 lanes x 8)
#define NBLK  148
#define NTHR  896               // 28 warps

// Dynamic smem layout (bytes)
#define OFF_SIDX 131072                   // after float4 tbl[8192]
#define OFF_UBS  147456                   // after u16 sidx[8192]
#define OFF_HIST 148512                   // float ubs[257] + pad
#define OFF_SOFF 150560
#define OFF_SCUR 152608
#define SMEM_TOTAL 154656

__device__ float d_part[NBLK];
__device__ int   d_done;                  // zero-init; self-resetting

__device__ __forceinline__ int bin_of(float n2) {
    int raw = (int)(n2 * INVW);
    raw = raw < 0 ? 0 : (raw > NBINS - 1 ? NBINS - 1 : raw);
    return NBINS - 1 - raw;               // bin 0 = highest norms
}

__global__ __launch_bounds__(NTHR, 1)
void vq_main_kernel(const float4* __restrict__ x4,
                    const float4* __restrict__ e4,
                    float* __restrict__ out) {
    extern __shared__ char smem[];
    float4*         s_tbl  = (float4*)smem;
    unsigned short* s_sidx = (unsigned short*)(smem + OFF_SIDX);
    float*          s_ubs  = (float*)(smem + OFF_UBS);
    int*            s_hist = (int*)(smem + OFF_HIST);
    int*            s_soff = (int*)(smem + OFF_SOFF);
    int*            s_scur = (int*)(smem + OFF_SCUR);
    __shared__ int   s_wsum[16];
    __shared__ float wred[NTHR / 32];
    __shared__ int   s_last;

    const int t    = threadIdx.x;
    const int lane = t & 31;
    const int wid  = t >> 5;
    const int sub  = lane & 3;
    const int tok  = ((int)blockIdx.x * 28 + wid) * 8 + (lane >> 2);
    const bool act = tok < NTOK;

    // Token load up-front: overlaps all of phase 1.
    float4 xv = act ? x4[tok] : make_float4(0.f, 0.f, 0.f, 0.f);
    const float nx = sqrtf(xv.x * xv.x + xv.y * xv.y + xv.z * xv.z + xv.w * xv.w)
                     * 1.000002f;                     // fp-guarded |x|

    // ---- Phase 1: per-block bin-sort of the table into smem ----
    for (int i = t; i < NBINS; i += NTHR) { s_hist[i] = 0; s_scur[i] = 0; }
    if (t == 0) { s_ubs[NEMB / 32] = 0.0f; s_last = 0; }
    __syncthreads();

    // histogram, 3 independent loads in flight
    for (int base = 0; base < NEMB; base += 3 * NTHR) {
        int i0 = base + t, i1 = i0 + NTHR, i2 = i1 + NTHR;
        float4 a, b, c;
        if (i0 < NEMB) a = e4[i0];
        if (i1 < NEMB) b = e4[i1];
        if (i2 < NEMB) c = e4[i2];
        if (i0 < NEMB) atomicAdd(&s_hist[bin_of(a.x*a.x + a.y*a.y + a.z*a.z + a.w*a.w)], 1);
        if (i1 < NEMB) atomicAdd(&s_hist[bin_of(b.x*b.x + b.y*b.y + b.z*b.z + b.w*b.w)], 1);
        if (i2 < NEMB) atomicAdd(&s_hist[bin_of(c.x*c.x + c.y*c.y + c.z*c.z + c.w*c.w)], 1);
    }
    __syncthreads();

    // exclusive prefix over 512 bins: 16 warp shfl-scans + top scan
    if (wid < 16) {
        int cnt = s_hist[wid * 32 + lane];
        int v = cnt;
        #pragma unroll
        for (int o = 1; o < 32; o <<= 1) {
            int u = __shfl_up_sync(0xFFFFFFFFu, v, o);
            if (lane >= o) v += u;
        }
        if (lane == 31) s_wsum[wid] = v;
        s_soff[wid * 32 + lane] = v - cnt;            // warp-local exclusive
    }
    __syncthreads();
    if (wid == 0) {
        int c2 = (lane < 16) ? s_wsum[lane] : 0;
        int v2 = c2;
        #pragma unroll
        for (int o = 1; o < 16; o <<= 1) {
            int u = __shfl_up_sync(0xFFFFFFFFu, v2, o);
            if (lane >= o) v2 += u;
        }
        if (lane < 16) s_wsum[lane] = v2 - c2;        // warp-group exclusive
    }
    __syncthreads();
    for (int i = t; i < NBINS; i += NTHR) s_soff[i] += s_wsum[i >> 5];
    __syncthreads();

    // scatter, 3 independent loads in flight
    for (int base = 0; base < NEMB; base += 3 * NTHR) {
        int id[3]; float4 ev[3];
        #pragma unroll
        for (int j = 0; j < 3; j++) {
            id[j] = base + t + j * NTHR;
            if (id[j] < NEMB) ev[j] = e4[id[j]];
        }
        #pragma unroll
        for (int j = 0; j < 3; j++) {
            if (id[j] < NEMB) {
                float4 e = ev[j];
                int b = bin_of(e.x*e.x + e.y*e.y + e.z*e.z + e.w*e.w);
                int pos = s_soff[b] + atomicAdd(&s_scur[b], 1);
                s_tbl[pos]  = e;
                s_sidx[pos] = (unsigned short)id[j];
                if ((pos & 31) == 0)      // ub non-increasing across slots
                    s_ubs[pos >> 5] = sqrtf((float)(NBINS - b) * BINW) * 1.000002f;
            }
        }
    }
    __syncthreads();

    // ---- Phase 2: pruned argmax scan, 4 lanes/token, quad-combined stop ----
    float best = act ? -CUDART_INF_F : CUDART_INF_F; // inactive: stop at once
    int bidx = NEMB;

    int p = 0;                                        // warp-uniform base
    for (;;) {
        float ubn = s_ubs[(p >> 5) + 1];              // bound on slots >= p+32
        float d[8];
        #pragma unroll
        for (int i = 0; i < 8; i++) {
            float4 e = s_tbl[p + sub + 4 * i];        // 4 words/warp: broadcast
            // identical FMA chain as all validated rounds
            d[i] = fmaf(xv.x, e.x, fmaf(xv.y, e.y, fmaf(xv.z, e.z, xv.w * e.w)));
        }
        float om = fmaxf(fmaxf(fmaxf(d[0], d[1]), fmaxf(d[2], d[3])),
                         fmaxf(fmaxf(d[4], d[5]), fmaxf(d[6], d[7])));
        if (om >= best) {
            // rare slow path: exact first-max update, original-id tie-break
            #pragma unroll
            for (int i = 0; i < 8; i++) {
                int id = (int)s_sidx[p + sub + 4 * i];
                if (d[i] > best || (d[i] == best && id < bidx)) {
                    best = d[i]; bidx = id;
                }
            }
        }
        // combined best across the quad (value only; exact ids merged later):
        // the strong certificate that lets all 4 lanes stop together.
        float cb = best;
        cb = fmaxf(cb, __shfl_xor_sync(0xFFFFFFFFu, cb, 1));
        cb = fmaxf(cb, __shfl_xor_sync(0xFFFFFFFFu, cb, 2));
        p += SSTEP;
        // every remaining slot has dot <= ubn*|x| < cb <= token best
        bool stop = (p >= NEMB) || (ubn * nx < cb);
        if (__all_sync(0xFFFFFFFFu, stop)) break;
    }

    // merge quad lanes: max value, ties -> lowest original index
    #pragma unroll
    for (int o = 1; o <= 2; o <<= 1) {
        float vo = __shfl_xor_sync(0xFFFFFFFFu, best, o);
        int   io = __shfl_xor_sync(0xFFFFFFFFu, bidx, o);
        if (vo > best || (vo == best && io < bidx)) { best = vo; bidx = io; }
    }

    float lsum = 0.0f;
    if (act && sub == 0) {
        float4 e = e4[bidx];
        lsum = fabsf(xv.x - e.x) + fabsf(xv.y - e.y)
             + fabsf(xv.z - e.z) + fabsf(xv.w - e.w);
    }

    // reduce: warp -> block
    #pragma unroll
    for (int o = 16; o; o >>= 1)
        lsum += __shfl_down_sync(0xFFFFFFFFu, lsum, o);
    if (lane == 0) wred[wid] = lsum;
    __syncthreads();

    // block partial -> d_part; last-arriving block finalizes (no init kernel)
    if (t == 0) {
        float s = 0.0f;
        #pragma unroll
        for (int i = 0; i < NTHR / 32; i++) s += wred[i];
        d_part[blockIdx.x] = s;
        __threadfence();
        if (atomicAdd(&d_done, 1) == NBLK - 1) s_last = 1;
    }
    __syncthreads();
    if (s_last && wid == 0) {
        float s = 0.0f;
        for (int i = lane; i < NBLK; i += 32) s += d_part[i];
        #pragma unroll
        for (int o = 16; o; o >>= 1)
            s += __shfl_down_sync(0xFFFFFFFFu, s, o);
        if (lane == 0) {
            out[0] = s * (2.0f / (float)(NTOK * 4));  // both L1 terms equal
            d_done = 0;                               // reset for graph replay
        }
    }
}

extern "C" void kernel_launch(void* const* d_in, const int* in_sizes, int n_in,
                              void* d_out, int out_size) {
    const float4* x   = (const float4*)d_in[0];   // [8,4096,4] f32
    const float4* emb = (const float4*)d_in[1];   // [8192,4] f32
    float* out = (float*)d_out;

    cudaFuncSetAttribute(vq_main_kernel,
                         cudaFuncAttributeMaxDynamicSharedMemorySize,
                         SMEM_TOTAL);

    vq_main_kernel<<<NBLK, NTHR, SMEM_TOTAL>>>(x, emb, out);
}

// round 12
// speedup vs baseline: 1.4291x; 1.0135x over previous
#include <cuda_runtime.h>
#include <math_constants.h>

#define NEMB  8192
#define NTOK  32768             // 8 * 4096
#define NBLK  148
#define NTHR  896               // 28 warps
#define CAP   1024              // staged-candidate capacity (mean ~750, +10 sigma)
#define THETA 8.0f              // ||e||^2 cutoff
#define NB2   64
#define WID2  0.5625f           // bin width over n2 in [8, 44)
#define IW2   (1.0f / 0.5625f)
#define SQ8G  (2.82842712f * 1.000002f)   // guarded sqrt(THETA)

__device__ float d_part[NBLK];
__device__ int   d_done;        // zero-init; self-resetting

__global__ __launch_bounds__(NTHR, 1)
void vq_main_kernel(const float4* __restrict__ x4,
                    const float4* __restrict__ e4,
                    float* __restrict__ out) {
    __shared__ float4 s_stage[CAP];     // unsorted candidates
    __shared__ float4 s_tbl[CAP];       // bin-sorted (desc norm)
    __shared__ int    s_sid[CAP];       // orig id (staged order)
    __shared__ int    s_sidx[CAP];      // orig id (sorted order)
    __shared__ int    s_hist[NB2], s_soff[NB2], s_scur[NB2];
    __shared__ float  s_ubs[CAP / 32 + 1];
    __shared__ float  wred[NTHR / 32];
    __shared__ int    s_cnt, s_last;

    const int t    = threadIdx.x;
    const int lane = t & 31;
    const int wid  = t >> 5;
    const int sub  = lane & 3;
    const int tok  = ((int)blockIdx.x * 28 + wid) * 8 + (lane >> 2);
    const bool act = tok < NTOK;

    float4 xv = act ? x4[tok] : make_float4(0.f, 0.f, 0.f, 0.f);
    const float nx = sqrtf(xv.x*xv.x + xv.y*xv.y + xv.z*xv.z + xv.w*xv.w)
                     * 1.000002f;                     // fp-guarded |x|

    // ---- Phase 1: stage only candidates with ||e||^2 >= THETA ----
    for (int i = t; i < NB2; i += NTHR) { s_hist[i] = 0; s_scur[i] = 0; }
    if (t == 0) { s_cnt = 0; s_last = 0; }
    __syncthreads();

    for (int base = 0; base < NEMB; base += 3 * NTHR) {   // 3 loads in flight
        int ii[3]; float4 ev[3];
        #pragma unroll
        for (int j = 0; j < 3; j++) {
            ii[j] = base + t + j * NTHR;
            if (ii[j] < NEMB) ev[j] = e4[ii[j]];
        }
        #pragma unroll
        for (int j = 0; j < 3; j++) {
            if (ii[j] < NEMB) {
                float4 e = ev[j];
                float n2 = e.x*e.x + e.y*e.y + e.z*e.z + e.w*e.w;
                if (n2 >= THETA) {
                    int pos = atomicAdd(&s_cnt, 1);
                    if (pos < CAP) {
                        s_stage[pos] = e; s_sid[pos] = ii[j];
                        int raw = (int)((n2 - THETA) * IW2);
                        raw = raw < 0 ? 0 : (raw > NB2 - 1 ? NB2 - 1 : raw);
                        atomicAdd(&s_hist[(NB2 - 1) - raw], 1);
                    }
                }
            }
        }
    }
    __syncthreads();
    const int  cnt  = s_cnt < CAP ? s_cnt : CAP;
    const bool over = s_cnt > CAP;      // ~never: forces exact full fallback

    // prefix over 64 bins (warp 0)
    if (wid == 0) {
        int a = s_hist[lane], b = s_hist[lane + 32];
        int va = a, vb = b;
        #pragma unroll
        for (int o = 1; o < 32; o <<= 1) {
            int u = __shfl_up_sync(0xFFFFFFFFu, va, o); if (lane >= o) va += u;
            int w = __shfl_up_sync(0xFFFFFFFFu, vb, o); if (lane >= o) vb += w;
        }
        int tot = __shfl_sync(0xFFFFFFFFu, va, 31);
        s_soff[lane]      = va - a;
        s_soff[lane + 32] = tot + vb - b;
    }
    __syncthreads();

    // smem-only scatter into bin-sorted order + superstep ub
    for (int i = t; i < cnt; i += NTHR) {
        float4 e = s_stage[i];
        float n2 = e.x*e.x + e.y*e.y + e.z*e.z + e.w*e.w;
        int raw = (int)((n2 - THETA) * IW2);
        raw = raw < 0 ? 0 : (raw > NB2 - 1 ? NB2 - 1 : raw);
        int b = (NB2 - 1) - raw;
        int pos = s_soff[b] + atomicAdd(&s_scur[b], 1);
        s_tbl[pos]  = e;
        s_sidx[pos] = s_sid[i];
        if ((pos & 31) == 0)            // ub for all slots >= pos (bin0 unbounded)
            s_ubs[pos >> 5] = (b == 0) ? CUDART_INF_F
                : sqrtf(THETA + (float)(NB2 - b) * WID2) * 1.000002f;
    }
    __syncthreads();

    // ---- Phase 2: pruned scan over <=cnt candidates, 4 lanes/token ----
    float best = act ? -CUDART_INF_F : CUDART_INF_F;
    int bidx = NEMB;
    const int nsl = (cnt + 31) & ~31;

    for (int p = 0; p < nsl; p += 32) {
        float ubn = (p + 32 >= cnt) ? SQ8G : s_ubs[(p >> 5) + 1];
        float d[8];
        #pragma unroll
        for (int i = 0; i < 8; i++) {
            int slot = p + sub + 4 * i;
            float4 e = s_tbl[slot];
            float dd = fmaf(xv.x, e.x, fmaf(xv.y, e.y, fmaf(xv.z, e.z, xv.w * e.w)));
            d[i] = (slot < cnt) ? dd : -CUDART_INF_F;
        }
        float om = fmaxf(fmaxf(fmaxf(d[0], d[1]), fmaxf(d[2], d[3])),
                         fmaxf(fmaxf(d[4], d[5]), fmaxf(d[6], d[7])));
        if (om >= best) {
            #pragma unroll
            for (int i = 0; i < 8; i++) {
                int slot = p + sub + 4 * i;
                int id = (slot < cnt) ? s_sidx[slot] : NEMB;
                if (d[i] > best || (d[i] == best && id < bidx)) {
                    best = d[i]; bidx = id;
                }
            }
        }
        float cb = best;                 // quad-combined best value
        cb = fmaxf(cb, __shfl_xor_sync(0xFFFFFFFFu, cb, 1));
        cb = fmaxf(cb, __shfl_xor_sync(0xFFFFFFFFu, cb, 2));
        // remaining tier slots <= ubn, non-tier mass <= SQ8G <= ubn
        if (!over && __all_sync(0xFFFFFFFFu, ubn * nx < cb)) break;
    }

    // final certificate; ~never false for real data
    float cbf = best;
    cbf = fmaxf(cbf, __shfl_xor_sync(0xFFFFFFFFu, cbf, 1));
    cbf = fmaxf(cbf, __shfl_xor_sync(0xFFFFFFFFu, cbf, 2));
    bool needFB = over ? act : !(SQ8G * nx < cbf);

    // exact warp-cooperative full-table fallback (correctness backstop)
    unsigned m = __ballot_sync(0xFFFFFFFFu, needFB);
    while (m) {
        int l = __ffs(m) - 1; int q = l >> 2;
        m &= ~(0xFu << (q << 2));
        int ol = q << 2;
        float tx = __shfl_sync(0xFFFFFFFFu, xv.x, ol);
        float ty = __shfl_sync(0xFFFFFFFFu, xv.y, ol);
        float tz = __shfl_sync(0xFFFFFFFFu, xv.z, ol);
        float tw = __shfl_sync(0xFFFFFFFFu, xv.w, ol);
        float lb = __shfl_sync(0xFFFFFFFFu, cbf, ol);   // seed: value-only bound
        int lid = NEMB;
        for (int pp = 0; pp < NEMB; pp += 256) {
            #pragma unroll
            for (int i = 0; i < 8; i++) {
                int slot = pp + lane + (i << 5);
                float4 e = e4[slot];
                float dd = fmaf(tx, e.x, fmaf(ty, e.y, fmaf(tz, e.z, tw * e.w)));
                if (dd > lb || (dd == lb && slot < lid)) { lb = dd; lid = slot; }
            }
        }
        #pragma unroll
        for (int o = 16; o; o >>= 1) {
            float vo = __shfl_xor_sync(0xFFFFFFFFu, lb, o);
            int   io = __shfl_xor_sync(0xFFFFFFFFu, lid, o);
            if (vo > lb || (vo == lb && io < lid)) { lb = vo; lid = io; }
        }
        if ((lane >> 2) == q) {
            if (lb > best || (lb == best && lid < bidx)) { best = lb; bidx = lid; }
        }
    }

    // merge quad lanes: max value, ties -> lowest original index
    #pragma unroll
    for (int o = 1; o <= 2; o <<= 1) {
        float vo = __shfl_xor_sync(0xFFFFFFFFu, best, o);
        int   io = __shfl_xor_sync(0xFFFFFFFFu, bidx, o);
        if (vo > best || (vo == best && io < bidx)) { best = vo; bidx = io; }
    }

    float lsum = 0.0f;
    if (act && sub == 0) {
        float4 e = e4[bidx];
        lsum = fabsf(xv.x - e.x) + fabsf(xv.y - e.y)
             + fabsf(xv.z - e.z) + fabsf(xv.w - e.w);
    }

    // reduce: warp -> block
    #pragma unroll
    for (int o = 16; o; o >>= 1)
        lsum += __shfl_down_sync(0xFFFFFFFFu, lsum, o);
    if (lane == 0) wred[wid] = lsum;
    __syncthreads();

    // block partial -> d_part; last-arriving block finalizes
    if (t == 0) {
        float s = 0.0f;
        #pragma unroll
        for (int i = 0; i < NTHR / 32; i++) s += wred[i];
        d_part[blockIdx.x] = s;
        __threadfence();
        if (atomicAdd(&d_done, 1) == NBLK - 1) s_last = 1;
    }
    __syncthreads();
    if (s_last && wid == 0) {
        float s = 0.0f;
        for (int i = lane; i < NBLK; i += 32) s += d_part[i];
        #pragma unroll
        for (int o = 16; o; o >>= 1)
            s += __shfl_down_sync(0xFFFFFFFFu, s, o);
        if (lane == 0) {
            out[0] = s * (2.0f / (float)(NTOK * 4));  // both L1 terms equal
            d_done = 0;                               // reset for graph replay
        }
    }
}

extern "C" void kernel_launch(void* const* d_in, const int* in_sizes, int n_in,
                              void* d_out, int out_size) {
    const float4* x   = (const float4*)d_in[0];   // [8,4096,4] f32
    const float4* emb = (const float4*)d_in[1];   // [8192,4] f32
    float* out = (float*)d_out;

    vq_main_kernel<<<NBLK, NTHR>>>(x, emb, out);
}